// round 15
// baseline (speedup 1.0000x reference)
#include <cuda_runtime.h>
#include <cuda_bf16.h>
#include <cuda_fp16.h>
#include <cstdint>

#define P_N 96
#define S_N 128
#define HN  8
#define HDN 32
#define LN  16
#define EN  256

__device__ __forceinline__ uint32_t smem_u32(const void* p) {
    uint32_t a;
    asm("{ .reg .u64 t; cvta.to.shared.u64 t, %1; cvt.u32.u64 %0, t; }" : "=r"(a) : "l"(p));
    return a;
}

#define LDSM4(r0, r1, r2, r3, addr)                                          \
    asm volatile("ldmatrix.sync.aligned.m8n8.x4.shared.b16 {%0,%1,%2,%3}, [%4];" \
                 : "=r"(r0), "=r"(r1), "=r"(r2), "=r"(r3) : "r"(addr))

#define MMA16816(d, a, b)                                                    \
    asm volatile("mma.sync.aligned.m16n8k16.row.col.f32.bf16.bf16.f32 "      \
                 "{%0,%1,%2,%3}, {%4,%5,%6,%7}, {%8,%9}, {%0,%1,%2,%3};"     \
                 : "+f"((d)[0]), "+f"((d)[1]), "+f"((d)[2]), "+f"((d)[3])    \
                 : "r"((a)[0]), "r"((a)[1]), "r"((a)[2]), "r"((a)[3]),       \
                   "r"((b)[0]), "r"((b)[1]))

#define MMAF16(d, a, b)                                                      \
    asm volatile("mma.sync.aligned.m16n8k16.row.col.f32.f16.f16.f32 "        \
                 "{%0,%1,%2,%3}, {%4,%5,%6,%7}, {%8,%9}, {%0,%1,%2,%3};"     \
                 : "+f"((d)[0]), "+f"((d)[1]), "+f"((d)[2]), "+f"((d)[3])    \
                 : "r"((a)[0]), "r"((a)[1]), "r"((a)[2]), "r"((a)[3]),       \
                   "r"((b)[0]), "r"((b)[1]))

// pack two fp32 -> f16x2 (first arg in low half)
__device__ __forceinline__ uint32_t packf16(float lo, float hi) {
    uint32_t d;
    asm("cvt.rn.f16x2.f32 %0, %1, %2;" : "=r"(d) : "f"(hi), "f"(lo));
    return d;
}
__device__ __forceinline__ uint32_t packh(__half lo, __half hi) {
    return ((uint32_t)__half_as_ushort(hi) << 16) | __half_as_ushort(lo);
}

// ---------------- scratch (device globals; no allocation allowed) ----------
__device__ uint32_t g_qs[P_N * HN * LN * 32];   // [hi(32bf16)|lo(32bf16)] per (p,h,i)
__device__ uint32_t g_ks[S_N * HN * LN * 32];
__device__ float g_vw[S_N * HN * LN];           // [s][h][j]
__device__ float g_c0;
__device__ float g_part[HN * P_N * S_N];        // per-head partial sums
__device__ int   g_cnt[192];                    // 16 sgroups x 12 pgroups

// pack two floats' bf16-hi and bf16-lo parts
__device__ __forceinline__ void split_pack(float f0, float f1, uint32_t& hw, uint32_t& lw) {
    __nv_bfloat16 h0 = __float2bfloat16(f0);
    __nv_bfloat16 h1 = __float2bfloat16(f1);
    __nv_bfloat16 l0 = __float2bfloat16(f0 - __bfloat162float(h0));
    __nv_bfloat16 l1 = __float2bfloat16(f1 - __bfloat162float(h1));
    hw = ((uint32_t)__bfloat16_as_ushort(h1) << 16) | __bfloat16_as_ushort(h0);
    lw = ((uint32_t)__bfloat16_as_ushort(l1) << 16) | __bfloat16_as_ushort(l0);
}

// ---------------- Q / K projection (HMMA) + fused prep+vw (spare blocks) ---
#define PROWB 144

__global__ void __launch_bounds__(256) proj_kernel(
        const float* __restrict__ pano, const float* __restrict__ sat,
        const float* __restrict__ in_w, const float* __restrict__ in_b,
        const float* __restrict__ Wo,   const float* __restrict__ bo,
        const float* __restrict__ Wop,  const float* __restrict__ bop) {
    const int z = blockIdx.z;
    const float* X;
    int woff;
    if (z == 0) { X = pano; woff = 0;  }
    else        { X = sat;  woff = EN; }

    if (z == 0 && blockIdx.x >= 24) {
        // ==== spare blocks: self-contained prep (weff -> Wvf, bvf, c0) + vw ====
        const int sid = (blockIdx.x - 24) * 4 + blockIdx.y;   // 0..31
        const int tid = threadIdx.x;
        __shared__ float sweff[EN];
        __shared__ float swvf[HN * 260];
        __shared__ float sbvf[HN];

        {
            float acc = 0.f;
            #pragma unroll 32
            for (int o = 0; o < EN; ++o)
                acc = fmaf(Wop[o], Wo[o * EN + tid], acc);
            sweff[tid] = acc;
        }
        __syncthreads();
        {
            float acc[HN] = {};
            #pragma unroll 32
            for (int hd = 0; hd < 256; ++hd)
                acc[hd >> 5] = fmaf(in_w[(2 * EN + hd) * EN + tid],
                                    sweff[hd], acc[hd >> 5]);
            #pragma unroll
            for (int h = 0; h < HN; ++h) swvf[h * 260 + tid] = acc[h];
        }
        if (tid < 8) {
            float b = 0.f;
            #pragma unroll
            for (int d = 0; d < HDN; ++d)
                b = fmaf(in_b[2 * EN + tid * HDN + d], sweff[tid * HDN + d], b);
            sbvf[tid] = b;
        }
        if (sid == 0) {
            __shared__ float red[EN];
            red[tid] = bo[tid] * Wop[tid];
            __syncthreads();
            for (int s = 128; s > 0; s >>= 1) {
                if (tid < s) red[tid] += red[tid + s];
                __syncthreads();
            }
            if (tid == 0) g_c0 = red[0] + bop[0];
        }
        __syncthreads();

        const int T = sid * 256 + tid;
        const int h = T & 7, r0 = T >> 3;
        const float bv = sbvf[h];
        const float* w = swvf + h * 260;
        const float4* __restrict__ x0 = (const float4*)(sat + r0 * EN);
        const float4* __restrict__ x1 = (const float4*)(sat + (r0 + 1024) * EN);
        float a0 = bv, a1 = bv;
        #pragma unroll 16
        for (int e4 = 0; e4 < 64; ++e4) {
            float4 b = *(const float4*)(w + e4 * 4);
            float4 v0 = x0[e4];
            float4 v1 = x1[e4];
            a0 = fmaf(v0.x, b.x, a0); a1 = fmaf(v1.x, b.x, a1);
            a0 = fmaf(v0.y, b.y, a0); a1 = fmaf(v1.y, b.y, a1);
            a0 = fmaf(v0.z, b.z, a0); a1 = fmaf(v1.z, b.z, a1);
            a0 = fmaf(v0.w, b.w, a0); a1 = fmaf(v1.w, b.w, a1);
        }
        g_vw[(r0 >> 4) * (HN * LN) + h * LN + (r0 & 15)] = a0;
        int r1 = r0 + 1024;
        g_vw[(r1 >> 4) * (HN * LN) + h * LN + (r1 & 15)] = a1;
        return;
    }

    // ==== HMMA GEMM path (unchanged) ====
    __shared__ __align__(16) char XS[64 * PROWB];
    __shared__ __align__(16) char WS[64 * PROWB];
    const uint32_t sbX = smem_u32(XS);
    const uint32_t sbW = smem_u32(WS);

    const int m0 = blockIdx.x * 64;
    const int n0 = blockIdx.y * 64;
    const int tid = threadIdx.x;
    const int warp = tid >> 5, lane = tid & 31;

    const int lrow = tid >> 2;
    const int kq   = tid & 3;
    const float* __restrict__ Xp = X + (m0 + lrow) * EN + kq * 8;
    const float* __restrict__ Wp = in_w + (woff + n0 + lrow) * EN + kq * 8;
    char* xrow = XS + lrow * PROWB;
    char* wrow = WS + lrow * PROWB;

    float acc[4][4];
    #pragma unroll
    for (int m = 0; m < 4; ++m)
        #pragma unroll
        for (int c = 0; c < 4; ++c) acc[m][c] = 0.f;

    float xb[8], wb[8];
    #pragma unroll
    for (int i = 0; i < 2; ++i) {
        *(float4*)(xb + i * 4) = *(const float4*)(Xp + i * 4);
        *(float4*)(wb + i * 4) = *(const float4*)(Wp + i * 4);
    }

    for (int c = 0; c < 8; ++c) {
        {
            uint32_t hx[4], lx[4], hw_[4], lw_[4];
            #pragma unroll
            for (int i = 0; i < 4; ++i) {
                split_pack(xb[2 * i], xb[2 * i + 1], hx[i], lx[i]);
                split_pack(wb[2 * i], wb[2 * i + 1], hw_[i], lw_[i]);
            }
            *(uint4*)(xrow + kq * 16)      = make_uint4(hx[0], hx[1], hx[2], hx[3]);
            *(uint4*)(xrow + 64 + kq * 16) = make_uint4(lx[0], lx[1], lx[2], lx[3]);
            *(uint4*)(wrow + kq * 16)      = make_uint4(hw_[0], hw_[1], hw_[2], hw_[3]);
            *(uint4*)(wrow + 64 + kq * 16) = make_uint4(lw_[0], lw_[1], lw_[2], lw_[3]);
        }
        __syncthreads();
        if (c < 7) {
            const float* xn = Xp + (c + 1) * 32;
            const float* wn = Wp + (c + 1) * 32;
            #pragma unroll
            for (int i = 0; i < 2; ++i) {
                *(float4*)(xb + i * 4) = *(const float4*)(xn + i * 4);
                *(float4*)(wb + i * 4) = *(const float4*)(wn + i * 4);
            }
        }

        uint32_t Bf[4][2];
        {
            uint32_t rowaddr = sbW + (warp * 8 + (lane & 7)) * PROWB + ((lane >> 3) * 16);
            LDSM4(Bf[0][0], Bf[0][1], Bf[1][0], Bf[1][1], rowaddr);
            LDSM4(Bf[2][0], Bf[2][1], Bf[3][0], Bf[3][1], rowaddr + 64);
        }
        #pragma unroll
        for (int m = 0; m < 4; ++m) {
            uint32_t A[4][4];
            uint32_t rowaddr = sbX + (m * 16 + (lane & 15)) * PROWB + ((lane >> 4) * 16);
            #pragma unroll
            for (int kb = 0; kb < 4; ++kb)
                LDSM4(A[kb][0], A[kb][1], A[kb][2], A[kb][3], rowaddr + kb * 32);
            MMA16816(acc[m], A[0], Bf[0]);
            MMA16816(acc[m], A[1], Bf[1]);
            MMA16816(acc[m], A[0], Bf[2]);
            MMA16816(acc[m], A[1], Bf[3]);
            MMA16816(acc[m], A[2], Bf[0]);
            MMA16816(acc[m], A[3], Bf[1]);
        }
        __syncthreads();
    }

    const int colp = n0 + warp * 8 + 2 * (lane & 3);
    const int h = colp >> 5, d = colp & 31;
    const float b0 = in_b[woff + colp];
    const float b1 = in_b[woff + colp + 1];
    #pragma unroll
    for (int m = 0; m < 4; ++m) {
        #pragma unroll
        for (int half = 0; half < 2; ++half) {
            int row = m0 + m * 16 + (lane >> 2) + half * 8;
            float va = acc[m][half * 2]     + b0;
            float vb = acc[m][half * 2 + 1] + b1;
            if (z == 0) { va *= 0.17677669529663687f; vb *= 0.17677669529663687f; }
            uint32_t hw, lw;
            split_pack(va, vb, hw, lw);
            int base = (((row >> 4) * HN + h) * LN + (row & 15)) * 32 + (d >> 1);
            if (z == 0) { g_qs[base] = hw; g_qs[base + 16] = lw; }
            else        { g_ks[base] = hw; g_ks[base + 16] = lw; }
        }
    }
}

// ---------------- HMMA attention + MMA softmax epilogue --------------------
// grid = (16 s-groups, 12 p-octets, 8 heads). 128 threads = 4 warps.
#define ROWB   144
#define QBASE  0
#define KBASE  18432                 // 128 rows * 144
#define VWBASE 36864                 // KBASE + 128*144
#define ASMEM_BYTES 37376            // VWBASE + 512

__global__ void __launch_bounds__(128) attn_mma_kernel(float* __restrict__ out) {
    extern __shared__ __align__(16) char smx[];
    const uint32_t sb = smem_u32(smx);
    const int tid = threadIdx.x;
    const int warp = tid >> 5, lane = tid & 31;
    const int u = lane & 3;
    const int bcol = lane >> 2;      // B-fragment n-column this lane supplies
    const int h = blockIdx.z;
    const int p0 = blockIdx.y * 8;
    const int s0 = blockIdx.x * 8;

    // ---- stage Q: 8 panos x 16 i rows ----
    {
        const uint4* __restrict__ src = (const uint4*)g_qs;
        #pragma unroll
        for (int tt = 0; tt < 8; ++tt) {
            int u2 = tid + tt * 128;
            int row = u2 >> 3, ch = u2 & 7;
            int pp = row >> 4, ii = row & 15;
            uint4 v = src[(((p0 + pp) * HN + h) * LN + ii) * 8 + ch];
            *(uint4*)(smx + QBASE + row * ROWB + ch * 16) = v;
        }
    }
    // ---- stage K: 8 sats x 16 j rows ----
    {
        const uint4* __restrict__ src = (const uint4*)g_ks;
        #pragma unroll
        for (int tt = 0; tt < 8; ++tt) {
            int u2 = tid + tt * 128;
            int row = u2 >> 3, ch = u2 & 7;
            int sp = row >> 4, jj = row & 15;
            uint4 v = src[(((s0 + sp) * HN + h) * LN + jj) * 8 + ch];
            *(uint4*)(smx + KBASE + row * ROWB + ch * 16) = v;
        }
    }
    // ---- stage vw [8 s'][16 j] ----
    if (tid < 128) {
        *(float*)(smx + VWBASE + tid * 4) =
            g_vw[(s0 + (tid >> 4)) * (HN * LN) + h * LN + (tid & 15)];
    }
    __syncthreads();

    const float* vws = (const float*)(smx + VWBASE);

    // ---- build fp16 B fragments: n-cols [vw_hi | vw_lo | ones | 0...] ----
    // B frag (k16xn8 col): lane holds k = 2u,2u+1 (b0) and 2u+8,2u+9 (b1), n = bcol.
    uint32_t Bv[2][2];
    #pragma unroll
    for (int npair = 0; npair < 2; ++npair) {
        int sl = warp * 2 + npair;
        float w0 = vws[sl * 16 + 2 * u];
        float w1 = vws[sl * 16 + 2 * u + 1];
        float w2 = vws[sl * 16 + 2 * u + 8];
        float w3 = vws[sl * 16 + 2 * u + 9];
        __half h0 = __float2half_rn(w0), h1 = __float2half_rn(w1);
        __half h2 = __float2half_rn(w2), h3 = __float2half_rn(w3);
        __half l0 = __float2half_rn(w0 - __half2float(h0));
        __half l1 = __float2half_rn(w1 - __half2float(h1));
        __half l2 = __float2half_rn(w2 - __half2float(h2));
        __half l3 = __float2half_rn(w3 - __half2float(h3));
        uint32_t b0, b1;
        if (bcol == 0)      { b0 = packh(h0, h1); b1 = packh(h2, h3); }
        else if (bcol == 1) { b0 = packh(l0, l1); b1 = packh(l2, l3); }
        else if (bcol == 2) { b0 = 0x3C003C00u;   b1 = 0x3C003C00u;   }
        else                { b0 = 0u;            b1 = 0u;            }
        Bv[npair][0] = b0;
        Bv[npair][1] = b1;
    }

    for (int iter = 0; iter < 4; ++iter) {
        uint32_t A[2][4][4];
        #pragma unroll
        for (int m = 0; m < 2; ++m) {
            int R0 = iter * 32 + m * 16;
            uint32_t rowaddr = sb + QBASE + (R0 + (lane & 15)) * ROWB + ((lane >> 4) * 16);
            #pragma unroll
            for (int kb = 0; kb < 4; ++kb)
                LDSM4(A[m][kb][0], A[m][kb][1], A[m][kb][2], A[m][kb][3],
                      rowaddr + kb * 32);
        }

        #pragma unroll
        for (int npair = 0; npair < 2; ++npair) {
            uint32_t Bf[2][4][2];
            #pragma unroll
            for (int nn = 0; nn < 2; ++nn) {
                int N0 = warp * 32 + (npair * 2 + nn) * 8;
                uint32_t rowaddr = sb + KBASE + (N0 + (lane & 7)) * ROWB + ((lane >> 3) * 16);
                LDSM4(Bf[nn][0][0], Bf[nn][0][1], Bf[nn][1][0], Bf[nn][1][1], rowaddr);
                LDSM4(Bf[nn][2][0], Bf[nn][2][1], Bf[nn][3][0], Bf[nn][3][1], rowaddr + 64);
            }

            float acc[2][2][4];
            #pragma unroll
            for (int m = 0; m < 2; ++m)
                #pragma unroll
                for (int nn = 0; nn < 2; ++nn)
                    #pragma unroll
                    for (int c = 0; c < 4; ++c) acc[m][nn][c] = 0.f;

            #pragma unroll
            for (int m = 0; m < 2; ++m)
                #pragma unroll
                for (int nn = 0; nn < 2; ++nn) {
                    MMA16816(acc[m][nn], A[m][0], Bf[nn][0]);  // qh.kh d0-15
                    MMA16816(acc[m][nn], A[m][1], Bf[nn][1]);  // qh.kh d16-31
                    MMA16816(acc[m][nn], A[m][0], Bf[nn][2]);  // qh.kl
                    MMA16816(acc[m][nn], A[m][1], Bf[nn][3]);
                    MMA16816(acc[m][nn], A[m][2], Bf[nn][0]);  // ql.kh
                    MMA16816(acc[m][nn], A[m][3], Bf[nn][1]);
                }

            int sl = warp * 2 + npair;

            #pragma unroll
            for (int m = 0; m < 2; ++m) {
                // exp(x-4) -> fp16 A fragment (C frag -> A frag, layout-exact)
                uint32_t Pa[4];
                Pa[0] = packf16(__expf(acc[m][0][0] - 4.f), __expf(acc[m][0][1] - 4.f));
                Pa[1] = packf16(__expf(acc[m][0][2] - 4.f), __expf(acc[m][0][3] - 4.f));
                Pa[2] = packf16(__expf(acc[m][1][0] - 4.f), __expf(acc[m][1][1] - 4.f));
                Pa[3] = packf16(__expf(acc[m][1][2] - 4.f), __expf(acc[m][1][3] - 4.f));

                float dnd[4] = {0.f, 0.f, 0.f, 0.f};
                MMAF16(dnd, Pa, Bv[npair]);

                // D frag (m16n8): lane holds cols {2u, 2u+1}, rows lane>>2 (+8).
                // u==0 lanes: cols 0,1 = num_hi+num_lo ; u==1 lanes: cols 2,3 = den+0.
                float s_lo = dnd[0] + dnd[1];     // row r = lane>>2
                float s_hi = dnd[2] + dnd[3];     // row r+8
                float o_lo = __shfl_xor_sync(0xffffffffu, s_lo, 1);
                float o_hi = __shfl_xor_sync(0xffffffffu, s_hi, 1);
                float v = 0.f;
                if (u == 0)
                    v = __fdividef(s_lo, o_lo) + __fdividef(s_hi, o_hi);
                v += __shfl_xor_sync(0xffffffffu, v, 1);
                v += __shfl_xor_sync(0xffffffffu, v, 2);
                v += __shfl_xor_sync(0xffffffffu, v, 4);
                v += __shfl_xor_sync(0xffffffffu, v, 8);
                v += __shfl_xor_sync(0xffffffffu, v, 16);

                if (lane == 0)
                    g_part[(h * P_N + p0 + iter * 2 + m) * S_N + s0 + sl] = v;
            }
        }
    }

    // ---- last block per (sgroup,pgroup) tile sums the 8 heads -> out ----
    __shared__ int s_last;
    __threadfence();
    __syncthreads();
    if (tid == 0) {
        int old = atomicAdd(&g_cnt[blockIdx.x * 12 + blockIdx.y], 1);
        s_last = (old == 7);
    }
    __syncthreads();
    if (s_last) {
        __threadfence();
        if (tid < 64) {
            int pp = tid >> 3, sl = tid & 7;
            float acc = 0.f;
            #pragma unroll
            for (int hh = 0; hh < HN; ++hh)
                acc += g_part[(hh * P_N + p0 + pp) * S_N + s0 + sl];
            out[(p0 + pp) * S_N + s0 + sl] = acc * (1.f / 16.f) + g_c0;
        }
        if (tid == 0) g_cnt[blockIdx.x * 12 + blockIdx.y] = 0;
    }
}

// ---------------- launch ---------------------------------------------------
extern "C" void kernel_launch(void* const* d_in, const int* in_sizes, int n_in,
                              void* d_out, int out_size) {
    const float* sat   = (const float*)d_in[0];
    const float* pano  = (const float*)d_in[1];
    const float* in_w  = (const float*)d_in[2];
    const float* in_b  = (const float*)d_in[3];
    const float* out_w = (const float*)d_in[4];
    const float* out_b = (const float*)d_in[5];
    const float* op_w  = (const float*)d_in[6];
    const float* op_b  = (const float*)d_in[7];
    float* out = (float*)d_out;

    cudaFuncSetAttribute(attn_mma_kernel, cudaFuncAttributeMaxDynamicSharedMemorySize,
                         ASMEM_BYTES);

    proj_kernel<<<dim3(32, 4, 2), 256>>>(pano, sat, in_w, in_b,
                                         out_w, out_b, op_w, op_b);
    attn_mma_kernel<<<dim3(16, 12, 8), 128, ASMEM_BYTES>>>(out);
}

// round 16
// speedup vs baseline: 1.0454x; 1.0454x over previous
#include <cuda_runtime.h>
#include <cuda_bf16.h>
#include <cstdint>

#define P_N 96
#define S_N 128
#define HN  8
#define HDN 32
#define LN  16
#define EN  256

__device__ __forceinline__ uint32_t smem_u32(const void* p) {
    uint32_t a;
    asm("{ .reg .u64 t; cvta.to.shared.u64 t, %1; cvt.u32.u64 %0, t; }" : "=r"(a) : "l"(p));
    return a;
}

#define LDSM4(r0, r1, r2, r3, addr)                                          \
    asm volatile("ldmatrix.sync.aligned.m8n8.x4.shared.b16 {%0,%1,%2,%3}, [%4];" \
                 : "=r"(r0), "=r"(r1), "=r"(r2), "=r"(r3) : "r"(addr))

#define MMA16816(d, a, b)                                                    \
    asm volatile("mma.sync.aligned.m16n8k16.row.col.f32.bf16.bf16.f32 "      \
                 "{%0,%1,%2,%3}, {%4,%5,%6,%7}, {%8,%9}, {%0,%1,%2,%3};"     \
                 : "+f"((d)[0]), "+f"((d)[1]), "+f"((d)[2]), "+f"((d)[3])    \
                 : "r"((a)[0]), "r"((a)[1]), "r"((a)[2]), "r"((a)[3]),       \
                   "r"((b)[0]), "r"((b)[1]))

// ---------------- scratch (device globals; no allocation allowed) ----------
__device__ uint32_t g_qs[P_N * HN * LN * 32];   // [hi(32bf16)|lo(32bf16)] per (p,h,i)
__device__ uint32_t g_ks[S_N * HN * LN * 32];
__device__ float g_vw[S_N * HN * LN];           // [s][h][j]
__device__ float g_c0;
__device__ float g_part[HN * P_N * S_N];        // per-head partial sums
__device__ int   g_cnt[192];                    // 16 sgroups x 12 pgroups

// pack two floats' bf16-hi and bf16-lo parts
__device__ __forceinline__ void split_pack(float f0, float f1, uint32_t& hw, uint32_t& lw) {
    __nv_bfloat16 h0 = __float2bfloat16(f0);
    __nv_bfloat16 h1 = __float2bfloat16(f1);
    __nv_bfloat16 l0 = __float2bfloat16(f0 - __bfloat162float(h0));
    __nv_bfloat16 l1 = __float2bfloat16(f1 - __bfloat162float(h1));
    hw = ((uint32_t)__bfloat16_as_ushort(h1) << 16) | __bfloat16_as_ushort(h0);
    lw = ((uint32_t)__bfloat16_as_ushort(l1) << 16) | __bfloat16_as_ushort(l0);
}

// ---------------- Q / K projection (HMMA) + fused prep+vw (spare blocks) ---
#define PROWB 144

__global__ void __launch_bounds__(256) proj_kernel(
        const float* __restrict__ pano, const float* __restrict__ sat,
        const float* __restrict__ in_w, const float* __restrict__ in_b,
        const float* __restrict__ Wo,   const float* __restrict__ bo,
        const float* __restrict__ Wop,  const float* __restrict__ bop) {
    const int z = blockIdx.z;
    const float* X;
    int woff;
    if (z == 0) { X = pano; woff = 0;  }
    else        { X = sat;  woff = EN; }

    if (z == 0 && blockIdx.x >= 24) {
        // ==== spare blocks: self-contained prep (weff -> Wvf, bvf, c0) + vw ====
        const int sid = (blockIdx.x - 24) * 4 + blockIdx.y;   // 0..31
        const int tid = threadIdx.x;
        __shared__ float sweff[EN];
        __shared__ float swvf[HN * 260];
        __shared__ float sbvf[HN];

        {
            float acc = 0.f;
            #pragma unroll 32
            for (int o = 0; o < EN; ++o)
                acc = fmaf(Wop[o], Wo[o * EN + tid], acc);
            sweff[tid] = acc;
        }
        __syncthreads();
        {
            float acc[HN] = {};
            #pragma unroll 32
            for (int hd = 0; hd < 256; ++hd)
                acc[hd >> 5] = fmaf(in_w[(2 * EN + hd) * EN + tid],
                                    sweff[hd], acc[hd >> 5]);
            #pragma unroll
            for (int h = 0; h < HN; ++h) swvf[h * 260 + tid] = acc[h];
        }
        if (tid < 8) {
            float b = 0.f;
            #pragma unroll
            for (int d = 0; d < HDN; ++d)
                b = fmaf(in_b[2 * EN + tid * HDN + d], sweff[tid * HDN + d], b);
            sbvf[tid] = b;
        }
        if (sid == 0) {
            __shared__ float red[EN];
            red[tid] = bo[tid] * Wop[tid];
            __syncthreads();
            for (int s = 128; s > 0; s >>= 1) {
                if (tid < s) red[tid] += red[tid + s];
                __syncthreads();
            }
            if (tid == 0) g_c0 = red[0] + bop[0];
        }
        __syncthreads();

        const int T = sid * 256 + tid;
        const int h = T & 7, r0 = T >> 3;
        const float bv = sbvf[h];
        const float* w = swvf + h * 260;
        const float4* __restrict__ x0 = (const float4*)(sat + r0 * EN);
        const float4* __restrict__ x1 = (const float4*)(sat + (r0 + 1024) * EN);
        float a0 = bv, a1 = bv;
        #pragma unroll 16
        for (int e4 = 0; e4 < 64; ++e4) {
            float4 b = *(const float4*)(w + e4 * 4);
            float4 v0 = x0[e4];
            float4 v1 = x1[e4];
            a0 = fmaf(v0.x, b.x, a0); a1 = fmaf(v1.x, b.x, a1);
            a0 = fmaf(v0.y, b.y, a0); a1 = fmaf(v1.y, b.y, a1);
            a0 = fmaf(v0.z, b.z, a0); a1 = fmaf(v1.z, b.z, a1);
            a0 = fmaf(v0.w, b.w, a0); a1 = fmaf(v1.w, b.w, a1);
        }
        g_vw[(r0 >> 4) * (HN * LN) + h * LN + (r0 & 15)] = a0;
        int r1 = r0 + 1024;
        g_vw[(r1 >> 4) * (HN * LN) + h * LN + (r1 & 15)] = a1;
        return;
    }

    // ==== HMMA GEMM path (unchanged) ====
    __shared__ __align__(16) char XS[64 * PROWB];
    __shared__ __align__(16) char WS[64 * PROWB];
    const uint32_t sbX = smem_u32(XS);
    const uint32_t sbW = smem_u32(WS);

    const int m0 = blockIdx.x * 64;
    const int n0 = blockIdx.y * 64;
    const int tid = threadIdx.x;
    const int warp = tid >> 5, lane = tid & 31;

    const int lrow = tid >> 2;
    const int kq   = tid & 3;
    const float* __restrict__ Xp = X + (m0 + lrow) * EN + kq * 8;
    const float* __restrict__ Wp = in_w + (woff + n0 + lrow) * EN + kq * 8;
    char* xrow = XS + lrow * PROWB;
    char* wrow = WS + lrow * PROWB;

    float acc[4][4];
    #pragma unroll
    for (int m = 0; m < 4; ++m)
        #pragma unroll
        for (int c = 0; c < 4; ++c) acc[m][c] = 0.f;

    float xb[8], wb[8];
    #pragma unroll
    for (int i = 0; i < 2; ++i) {
        *(float4*)(xb + i * 4) = *(const float4*)(Xp + i * 4);
        *(float4*)(wb + i * 4) = *(const float4*)(Wp + i * 4);
    }

    for (int c = 0; c < 8; ++c) {
        {
            uint32_t hx[4], lx[4], hw_[4], lw_[4];
            #pragma unroll
            for (int i = 0; i < 4; ++i) {
                split_pack(xb[2 * i], xb[2 * i + 1], hx[i], lx[i]);
                split_pack(wb[2 * i], wb[2 * i + 1], hw_[i], lw_[i]);
            }
            *(uint4*)(xrow + kq * 16)      = make_uint4(hx[0], hx[1], hx[2], hx[3]);
            *(uint4*)(xrow + 64 + kq * 16) = make_uint4(lx[0], lx[1], lx[2], lx[3]);
            *(uint4*)(wrow + kq * 16)      = make_uint4(hw_[0], hw_[1], hw_[2], hw_[3]);
            *(uint4*)(wrow + 64 + kq * 16) = make_uint4(lw_[0], lw_[1], lw_[2], lw_[3]);
        }
        __syncthreads();
        if (c < 7) {
            const float* xn = Xp + (c + 1) * 32;
            const float* wn = Wp + (c + 1) * 32;
            #pragma unroll
            for (int i = 0; i < 2; ++i) {
                *(float4*)(xb + i * 4) = *(const float4*)(xn + i * 4);
                *(float4*)(wb + i * 4) = *(const float4*)(wn + i * 4);
            }
        }

        uint32_t Bf[4][2];
        {
            uint32_t rowaddr = sbW + (warp * 8 + (lane & 7)) * PROWB + ((lane >> 3) * 16);
            LDSM4(Bf[0][0], Bf[0][1], Bf[1][0], Bf[1][1], rowaddr);
            LDSM4(Bf[2][0], Bf[2][1], Bf[3][0], Bf[3][1], rowaddr + 64);
        }
        #pragma unroll
        for (int m = 0; m < 4; ++m) {
            uint32_t A[4][4];
            uint32_t rowaddr = sbX + (m * 16 + (lane & 15)) * PROWB + ((lane >> 4) * 16);
            #pragma unroll
            for (int kb = 0; kb < 4; ++kb)
                LDSM4(A[kb][0], A[kb][1], A[kb][2], A[kb][3], rowaddr + kb * 32);
            MMA16816(acc[m], A[0], Bf[0]);
            MMA16816(acc[m], A[1], Bf[1]);
            MMA16816(acc[m], A[0], Bf[2]);
            MMA16816(acc[m], A[1], Bf[3]);
            MMA16816(acc[m], A[2], Bf[0]);
            MMA16816(acc[m], A[3], Bf[1]);
        }
        __syncthreads();
    }

    const int colp = n0 + warp * 8 + 2 * (lane & 3);
    const int h = colp >> 5, d = colp & 31;
    const float b0 = in_b[woff + colp];
    const float b1 = in_b[woff + colp + 1];
    #pragma unroll
    for (int m = 0; m < 4; ++m) {
        #pragma unroll
        for (int half = 0; half < 2; ++half) {
            int row = m0 + m * 16 + (lane >> 2) + half * 8;
            float va = acc[m][half * 2]     + b0;
            float vb = acc[m][half * 2 + 1] + b1;
            if (z == 0) { va *= 0.17677669529663687f; vb *= 0.17677669529663687f; }
            uint32_t hw, lw;
            split_pack(va, vb, hw, lw);
            int base = (((row >> 4) * HN + h) * LN + (row & 15)) * 32 + (d >> 1);
            if (z == 0) { g_qs[base] = hw; g_qs[base + 16] = lw; }
            else        { g_ks[base] = hw; g_ks[base + 16] = lw; }
        }
    }
}

// ---------------- HMMA attention + in-kernel final reduce ------------------
// grid = (16 s-groups, 12 p-octets, 8 heads). 256 threads = 8 warps.
// Block tile: 8 panos x 8 sats x 1 head. Warp = 1 sat; B frags hoisted.
#define ROWB   144
#define QBASE  0
#define KBASE  18432                 // 128 rows * 144
#define VWBASE 36864                 // KBASE + 128*144
#define ASMEM_BYTES 37376            // VWBASE + 512

__global__ void __launch_bounds__(256) attn_mma_kernel(float* __restrict__ out) {
    extern __shared__ __align__(16) char smx[];
    const uint32_t sb = smem_u32(smx);
    const int tid = threadIdx.x;
    const int warp = tid >> 5, lane = tid & 31;
    const int t = lane & 3;
    const int h = blockIdx.z;
    const int p0 = blockIdx.y * 8;
    const int s0 = blockIdx.x * 8;

    // ---- stage Q: 8 panos x 16 i rows (1024 uint4) ----
    {
        const uint4* __restrict__ src = (const uint4*)g_qs;
        #pragma unroll
        for (int tt = 0; tt < 4; ++tt) {
            int u2 = tid + tt * 256;
            int row = u2 >> 3, ch = u2 & 7;
            int pp = row >> 4, ii = row & 15;
            uint4 v = src[(((p0 + pp) * HN + h) * LN + ii) * 8 + ch];
            *(uint4*)(smx + QBASE + row * ROWB + ch * 16) = v;
        }
    }
    // ---- stage K: 8 sats x 16 j rows (1024 uint4) ----
    {
        const uint4* __restrict__ src = (const uint4*)g_ks;
        #pragma unroll
        for (int tt = 0; tt < 4; ++tt) {
            int u2 = tid + tt * 256;
            int row = u2 >> 3, ch = u2 & 7;
            int sp = row >> 4, jj = row & 15;
            uint4 v = src[(((s0 + sp) * HN + h) * LN + jj) * 8 + ch];
            *(uint4*)(smx + KBASE + row * ROWB + ch * 16) = v;
        }
    }
    // ---- stage vw [8 s'][16 j] ----
    if (tid < 128) {
        *(float*)(smx + VWBASE + tid * 4) =
            g_vw[(s0 + (tid >> 4)) * (HN * LN) + h * LN + (tid & 15)];
    }
    __syncthreads();

    const float* vws = (const float*)(smx + VWBASE);

    // ---- hoist B fragments for THIS warp's sat (iter-invariant, 16 regs) ----
    uint32_t Bf[2][4][2];
    #pragma unroll
    for (int nn = 0; nn < 2; ++nn) {
        int N0 = warp * 16 + nn * 8;
        uint32_t rowaddr = sb + KBASE + (N0 + (lane & 7)) * ROWB + ((lane >> 3) * 16);
        LDSM4(Bf[nn][0][0], Bf[nn][0][1], Bf[nn][1][0], Bf[nn][1][1], rowaddr);
        LDSM4(Bf[nn][2][0], Bf[nn][2][1], Bf[nn][3][0], Bf[nn][3][1], rowaddr + 64);
    }

    const float vw0 = vws[warp * 16 + 2 * t];
    const float vw1 = vws[warp * 16 + 2 * t + 1];
    const float vw2 = vws[warp * 16 + 2 * t + 8];
    const float vw3 = vws[warp * 16 + 2 * t + 9];

    for (int iter = 0; iter < 4; ++iter) {
        uint32_t A[2][4][4];
        #pragma unroll
        for (int m = 0; m < 2; ++m) {
            int R0 = iter * 32 + m * 16;
            uint32_t rowaddr = sb + QBASE + (R0 + (lane & 15)) * ROWB + ((lane >> 4) * 16);
            #pragma unroll
            for (int kb = 0; kb < 4; ++kb)
                LDSM4(A[m][kb][0], A[m][kb][1], A[m][kb][2], A[m][kb][3],
                      rowaddr + kb * 32);
        }

        float acc[2][2][4];
        #pragma unroll
        for (int m = 0; m < 2; ++m)
            #pragma unroll
            for (int nn = 0; nn < 2; ++nn)
                #pragma unroll
                for (int c = 0; c < 4; ++c) acc[m][nn][c] = 0.f;

        #pragma unroll
        for (int m = 0; m < 2; ++m)
            #pragma unroll
            for (int nn = 0; nn < 2; ++nn) {
                MMA16816(acc[m][nn], A[m][0], Bf[nn][0]);  // qh.kh d0-15
                MMA16816(acc[m][nn], A[m][1], Bf[nn][1]);  // qh.kh d16-31
                MMA16816(acc[m][nn], A[m][0], Bf[nn][2]);  // qh.kl
                MMA16816(acc[m][nn], A[m][1], Bf[nn][3]);
                MMA16816(acc[m][nn], A[m][2], Bf[nn][0]);  // ql.kh
                MMA16816(acc[m][nn], A[m][3], Bf[nn][1]);
            }

        #pragma unroll
        for (int m = 0; m < 2; ++m) {
            float e0 = __expf(acc[m][0][0]);
            float e1 = __expf(acc[m][0][1]);
            float e2 = __expf(acc[m][1][0]);
            float e3 = __expf(acc[m][1][1]);
            float num = e0 * vw0 + e1 * vw1 + e2 * vw2 + e3 * vw3;
            float den = e0 + e1 + e2 + e3;
            float f0 = __expf(acc[m][0][2]);
            float f1 = __expf(acc[m][0][3]);
            float f2 = __expf(acc[m][1][2]);
            float f3 = __expf(acc[m][1][3]);
            float numh = f0 * vw0 + f1 * vw1 + f2 * vw2 + f3 * vw3;
            float denh = f0 + f1 + f2 + f3;

            num  += __shfl_xor_sync(0xffffffffu, num, 1);
            den  += __shfl_xor_sync(0xffffffffu, den, 1);
            numh += __shfl_xor_sync(0xffffffffu, numh, 1);
            denh += __shfl_xor_sync(0xffffffffu, denh, 1);
            num  += __shfl_xor_sync(0xffffffffu, num, 2);
            den  += __shfl_xor_sync(0xffffffffu, den, 2);
            numh += __shfl_xor_sync(0xffffffffu, numh, 2);
            denh += __shfl_xor_sync(0xffffffffu, denh, 2);

            float val = __fdividef(num, den) + __fdividef(numh, denh);
            val += __shfl_xor_sync(0xffffffffu, val, 4);
            val += __shfl_xor_sync(0xffffffffu, val, 8);
            val += __shfl_xor_sync(0xffffffffu, val, 16);

            if (lane == 0)
                g_part[(h * P_N + p0 + iter * 2 + m) * S_N + s0 + warp] = val;
        }
    }

    // ---- last block per (sgroup,pgroup) tile sums the 8 heads -> out ----
    __shared__ int s_last;
    __threadfence();
    __syncthreads();
    if (tid == 0) {
        int old = atomicAdd(&g_cnt[blockIdx.x * 12 + blockIdx.y], 1);
        s_last = (old == 7);
    }
    __syncthreads();
    if (s_last) {
        __threadfence();
        if (tid < 64) {
            int pp = tid >> 3, sl = tid & 7;
            float acc = 0.f;
            #pragma unroll
            for (int hh = 0; hh < HN; ++hh)
                acc += g_part[(hh * P_N + p0 + pp) * S_N + s0 + sl];
            out[(p0 + pp) * S_N + s0 + sl] = acc * (1.f / 16.f) + g_c0;
        }
        if (tid == 0) g_cnt[blockIdx.x * 12 + blockIdx.y] = 0;
    }
}

// ---------------- launch ---------------------------------------------------
extern "C" void kernel_launch(void* const* d_in, const int* in_sizes, int n_in,
                              void* d_out, int out_size) {
    const float* sat   = (const float*)d_in[0];
    const float* pano  = (const float*)d_in[1];
    const float* in_w  = (const float*)d_in[2];
    const float* in_b  = (const float*)d_in[3];
    const float* out_w = (const float*)d_in[4];
    const float* out_b = (const float*)d_in[5];
    const float* op_w  = (const float*)d_in[6];
    const float* op_b  = (const float*)d_in[7];
    float* out = (float*)d_out;

    cudaFuncSetAttribute(attn_mma_kernel, cudaFuncAttributeMaxDynamicSharedMemorySize,
                         ASMEM_BYTES);

    proj_kernel<<<dim3(32, 4, 2), 256>>>(pano, sat, in_w, in_b,
                                         out_w, out_b, op_w, op_b);
    attn_mma_kernel<<<dim3(16, 12, 8), 256, ASMEM_BYTES>>>(out);
}